// round 11
// baseline (speedup 1.0000x reference)
#include <cuda_runtime.h>
#include <cuda_fp16.h>
#include <mma.h>
#include <cstdint>

using namespace nvcuda;

// Problem constants
#define B_WIN   4096
#define NTOK    49
#define CDIM    384
#define NHEADS  12
#define HDIM    32
#define NWIN    1024
#define SCALE_Q 0.17677669529663687f  // 32^-0.5

// Precomputed-weight globals (~1.5 MB)
__device__ __align__(256) __half g_wqkv[NHEADS * 96 * CDIM];  // head-permuted qkv_w
__device__ __align__(256) __half g_wpj_h[CDIM * CDIM];        // proj_w hi
__device__ __align__(256) __half g_wpj_l[CDIM * CDIM];        // proj_w lo

// Shared memory layout (byte offsets)
#define SM_XH   0        // Xh: 64 x 392 half = 50176
#define SM_SF   50176    // GEMM staging 64x196 f32 | S 2x64x68 f32 + Sh 2x64x72 half
#define SM_WB   103424   // 2 buffers x 15360 halves (30720 B each); buf0 aliases qkv
#define SM_OH   164864   // Oh: 64 x 392 half = 50176
#define SM_MS   215040   // mask fp16: 49 x 50 = 4900 (+pad)
#define SM_RB   219952   // rpb all heads fp16: 12 x 169 = 4056 (+pad)
#define SM_PAR  224016   // qkv_b(1152)+proj_b(384)+lamb(12) f32 = 6192
#define SMEM_BYTES 230208

#define XLD   392        // Xh/Oh ld (halves)
#define WLD   72         // weight staging ld (halves)
#define WBUFH 15360      // halves per WB buffer
#define KVLD  40         // qkv ld (halves)
#define QLD   196        // GEMM staging ld (floats)
#define SLD   68         // S f32 ld
#define SHLD  72         // Sh ld (halves)
#define PQLD  100        // proj staging ld (floats)
#define SH_OFF 34816     // byte offset of Sh inside SF region
#define PLOFF 6912       // proj lo offset within a buffer (halves)
#define NT    512

// ---------------------------------------------------------------------------
__device__ __forceinline__ void cpasync16(unsigned dst, const void* src)
{
    asm volatile("cp.async.cg.shared.global [%0], [%1], 16;\n" :: "r"(dst), "l"(src));
}
__device__ __forceinline__ void cp_commit() { asm volatile("cp.async.commit_group;\n"); }
__device__ __forceinline__ void cp_wait0()  { asm volatile("cp.async.wait_group 0;\n"); }
__device__ __forceinline__ unsigned smem_u32(const void* p)
{
    return (unsigned)__cvta_generic_to_shared(p);
}

// ---------------------------------------------------------------------------
__global__ void prep_qkv_w(const float* __restrict__ qkv_w)
{
    int idx = blockIdx.x * 256 + threadIdx.x;
    if (idx < NHEADS * 96 * CDIM) {
        int h   = idx / (96 * CDIM);
        int rem = idx % (96 * CDIM);
        int j   = rem / CDIM;
        int k   = rem % CDIM;
        int g   = (j >> 5) * CDIM + h * HDIM + (j & 31);
        g_wqkv[idx] = __float2half_rn(qkv_w[(size_t)g * CDIM + k]);
    }
}

__global__ void prep_proj_w(const float* __restrict__ proj_w)
{
    int idx = blockIdx.x * 256 + threadIdx.x;
    if (idx < CDIM * CDIM) {
        float v = proj_w[idx];
        __half hi = __float2half_rn(v);
        g_wpj_h[idx] = hi;
        g_wpj_l[idx] = __float2half_rn(v - __half2float(hi));
    }
}

// ---------------------------------------------------------------------------
// Fused window attention: one block per window, 512 threads, head-pair groups,
// cp.async double-buffered weight staging with cross-phase prefetch.
// ---------------------------------------------------------------------------
__global__ void __launch_bounds__(NT, 1)
winattn_kernel(const float* __restrict__ x,
               const float* __restrict__ mask,
               const float* __restrict__ qkv_b,
               const float* __restrict__ proj_b,
               const float* __restrict__ rpb,
               const float* __restrict__ lamb,
               float* __restrict__ out)
{
    extern __shared__ __align__(16) char smraw[];
    __half* Xh  = (__half*)(smraw + SM_XH);
    float*  Sf  = (float*)(smraw + SM_SF);
    __half* Sh  = (__half*)(smraw + SM_SF + SH_OFF);
    __half* WB  = (__half*)(smraw + SM_WB);
    __half* qkv = (__half*)(smraw + SM_WB);            // aliases WB buffer 0
    __half* Oh  = (__half*)(smraw + SM_OH);
    __half* ms  = (__half*)(smraw + SM_MS);
    __half* rb  = (__half*)(smraw + SM_RB);
    float*  par = (float*)(smraw + SM_PAR);

    const int tid = threadIdx.x;
    const int wp  = tid >> 5;
    const int l   = tid & 31;
    const int w   = blockIdx.x;

    // per-thread staging map: 192x64-half chunk = 1536 int4, 3 per thread
    int sj[3], sk[3];
#pragma unroll
    for (int i = 0; i < 3; ++i) {
        int v = tid + i * NT;
        sj[i] = v >> 3;
        sk[i] = (v & 7) << 3;
    }
    // proj staging map: hi(768 int4) + lo(768 int4)
    int pj[3], pk[3], psel[3];
#pragma unroll
    for (int i = 0; i < 3; ++i) {
        int v = tid + i * NT;
        psel[i] = (v >= 768);
        int v2 = v - psel[i] * 768;
        pj[i] = v2 >> 3;
        pk[i] = (v2 & 7) << 3;
    }

    // ---- init ----
    for (int t = tid; t < 49 * 96; t += NT) {
        int r = t / 96, c4 = (t % 96) * 4;
        float4 v = *(const float4*)&x[((size_t)w * NTOK + r) * CDIM + c4];
        *(__half2*)&Xh[r * XLD + c4]     = __floats2half2_rn(v.x, v.y);
        *(__half2*)&Xh[r * XLD + c4 + 2] = __floats2half2_rn(v.z, v.w);
    }
    for (int t = tid; t < 15 * 196; t += NT) {
        int r = 49 + t / 196, c2 = (t % 196) * 2;
        __half2 z = __floats2half2_rn(0.0f, 0.0f);
        *(__half2*)&Xh[r * XLD + c2] = z;
        *(__half2*)&Oh[r * XLD + c2] = z;
    }
    {
        const float* mrow = mask + (size_t)(w & (NWIN - 1)) * (NTOK * NTOK);
        for (int t = tid; t < NTOK * NTOK; t += NT)
            ms[(t / 49) * 50 + (t % 49)] = __float2half_rn(mrow[t]);
    }
    for (int t = tid; t < NHEADS * 169; t += NT)
        rb[t] = __float2half_rn(rpb[(t % 169) * NHEADS + (t / 169)]);
    for (int t = tid; t < 1548; t += NT)
        par[t] = (t < 1152) ? qkv_b[t] : (t < 1536 ? proj_b[t - 1152] : lamb[t - 1536]);
    __syncthreads();

    // prefetch group 0 chunk 0 -> buf1
    {
        const __half* Wg0 = g_wqkv;
        __half* dst = WB + WBUFH;
#pragma unroll
        for (int i = 0; i < 3; ++i)
            cpasync16(smem_u32(dst + sj[i] * WLD + sk[i]),
                      Wg0 + (size_t)sj[i] * CDIM + sk[i]);
        cp_commit();
    }

    const int mt = wp & 3;           // GEMM m-tile (16 rows)
    const int nb = (wp >> 2) * 48;   // QKV GEMM n-base

    // =============== 6 groups of 2 heads ===============
    for (int g = 0; g < 6; ++g) {
        const int h0 = 2 * g;
        const __half* Wg = g_wqkv + (size_t)h0 * (96 * CDIM);

        // ---- QKV GEMM: 64x192 = Xh @ Wg^T, Kc=64, cp.async double-buffered ----
        wmma::fragment<wmma::accumulator, 16, 16, 16, float> acc[3];
#pragma unroll
        for (int j = 0; j < 3; ++j) wmma::fill_fragment(acc[j], 0.0f);

        for (int c = 0; c < 6; ++c) {
            cp_wait0();
            __syncthreads();
            if (c < 5) {   // issue chunk c+1 into buf[c&1]
                __half* dst = WB + (c & 1) * WBUFH;
#pragma unroll
                for (int i = 0; i < 3; ++i)
                    cpasync16(smem_u32(dst + sj[i] * WLD + sk[i]),
                              Wg + (size_t)sj[i] * CDIM + (c + 1) * 64 + sk[i]);
                cp_commit();
            }
            const __half* Wc = WB + (1 - (c & 1)) * WBUFH;   // chunk c lives here
#pragma unroll
            for (int ks = 0; ks < 4; ++ks) {
                wmma::fragment<wmma::matrix_a, 16, 16, 16, __half, wmma::row_major> a1;
                wmma::load_matrix_sync(a1, &Xh[mt * 16 * XLD + c * 64 + ks * 16], XLD);
#pragma unroll
                for (int j = 0; j < 3; ++j) {
                    wmma::fragment<wmma::matrix_b, 16, 16, 16, __half, wmma::col_major> b1;
                    wmma::load_matrix_sync(b1, &Wc[(nb + j * 16) * WLD + ks * 16], WLD);
                    wmma::mma_sync(acc[j], a1, b1, acc[j]);
                }
            }
        }
#pragma unroll
        for (int j = 0; j < 3; ++j)
            wmma::store_matrix_sync(&Sf[mt * 16 * QLD + nb + j * 16], acc[j],
                                    QLD, wmma::mem_row_major);
        __syncthreads();

        // prefetch next group's chunk 0 -> buf1 (buf0 becomes qkv)
        if (g < 5) {
            const __half* Wn = g_wqkv + (size_t)(h0 + 2) * (96 * CDIM);
            __half* dst = WB + WBUFH;
#pragma unroll
            for (int i = 0; i < 3; ++i)
                cpasync16(smem_u32(dst + sj[i] * WLD + sk[i]),
                          Wn + (size_t)sj[i] * CDIM + sk[i]);
            cp_commit();
        }

        // ---- bias + q-scale + convert -> qkv fp16 (buf0) ----
        for (int t = tid; t < 49 * 192; t += NT) {
            int r = t / 192, cc = t % 192;
            int hh = cc / 96, c2 = cc % 96, which = c2 >> 5, d = c2 & 31;
            float vv = Sf[r * QLD + cc] + par[which * CDIM + (h0 + hh) * HDIM + d];
            if (which == 0) vv *= SCALE_Q;
            qkv[hh * 7680 + which * 2560 + r * KVLD + d] = __float2half_rn(vv);
        }
        __syncthreads();

        // ---- S = q @ k^T : 32 tiles over 16 warps ----
        for (int t = wp; t < 32; t += 16) {
            int hh = t >> 4, mi = (t >> 2) & 3, nj = t & 3;
            const __half* qh = qkv + hh * 7680;
            const __half* kh = qh + 2560;
            wmma::fragment<wmma::accumulator, 16, 16, 16, float> sacc;
            wmma::fill_fragment(sacc, 0.0f);
#pragma unroll
            for (int ks = 0; ks < 2; ++ks) {
                wmma::fragment<wmma::matrix_a, 16, 16, 16, __half, wmma::row_major> a1;
                wmma::fragment<wmma::matrix_b, 16, 16, 16, __half, wmma::col_major> b1;
                wmma::load_matrix_sync(a1, &qh[mi * 16 * KVLD + ks * 16], KVLD);
                wmma::load_matrix_sync(b1, &kh[nj * 16 * KVLD + ks * 16], KVLD);
                wmma::mma_sync(sacc, a1, b1, sacc);
            }
            wmma::store_matrix_sync(&Sf[hh * 4352 + mi * 16 * SLD + nj * 16],
                                    sacc, SLD, wmma::mem_row_major);
        }
        __syncthreads();

        // ---- softmax (+rpb+mask, lamb rescale) -> Sh fp16; zero pads ----
        for (int i2 = wp; i2 < 128; i2 += 16) {
            int hh = i2 >> 6, i = i2 & 63;
            __half* ShH = Sh + hh * 4608;
            if (i < NTOK) {
                const float lam1 = 1.0f + par[1536 + h0 + hh];
                const float invn = 1.0f / (float)NTOK;
                const __half* rbh = rb + (h0 + hh) * 169;
                const int i7 = i / 7, im = i - i7 * 7;
                const int j0 = l, j1 = l + 32;
                const int r0 = (i7 - j0 / 7 + 6) * 13 + (im - j0 % 7 + 6);
                float s0 = Sf[hh * 4352 + i * SLD + j0] + __half2float(rbh[r0])
                         + __half2float(ms[i * 50 + j0]);
                float s1 = -1e30f;
                if (j1 < NTOK) {
                    const int r1 = (i7 - j1 / 7 + 6) * 13 + (im - j1 % 7 + 6);
                    s1 = Sf[hh * 4352 + i * SLD + j1] + __half2float(rbh[r1])
                       + __half2float(ms[i * 50 + j1]);
                }
                float mx = fmaxf(s0, s1);
#pragma unroll
                for (int off = 16; off > 0; off >>= 1)
                    mx = fmaxf(mx, __shfl_xor_sync(0xffffffffu, mx, off));
                float e0 = __expf(s0 - mx);
                float e1 = (j1 < NTOK) ? __expf(s1 - mx) : 0.0f;
                float sm = e0 + e1;
#pragma unroll
                for (int off = 16; off > 0; off >>= 1)
                    sm += __shfl_xor_sync(0xffffffffu, sm, off);
                const float inv = 1.0f / sm;
                ShH[i * SHLD + j0] = __float2half_rn(invn + (e0 * inv - invn) * lam1);
                ShH[i * SHLD + j1] = (j1 < NTOK)
                    ? __float2half_rn(invn + (e1 * inv - invn) * lam1)
                    : __float2half_rn(0.0f);
            } else {
                ShH[i * SHLD + l]      = __float2half_rn(0.0f);
                ShH[i * SHLD + l + 32] = __float2half_rn(0.0f);
            }
        }
        __syncthreads();

        // ---- O = attn @ v : 16 tiles, 1 per warp ----
        {
            int hh = wp >> 3, mi = (wp >> 1) & 3, nj = wp & 1;
            const __half* ShH = Sh + hh * 4608;
            const __half* vhh = qkv + hh * 7680 + 5120;
            wmma::fragment<wmma::accumulator, 16, 16, 16, float> oacc;
            wmma::fill_fragment(oacc, 0.0f);
#pragma unroll
            for (int ks = 0; ks < 4; ++ks) {
                wmma::fragment<wmma::matrix_a, 16, 16, 16, __half, wmma::row_major> a1;
                wmma::fragment<wmma::matrix_b, 16, 16, 16, __half, wmma::row_major> b1;
                wmma::load_matrix_sync(a1, &ShH[mi * 16 * SHLD + ks * 16], SHLD);
                wmma::load_matrix_sync(b1, &vhh[ks * 16 * KVLD + nj * 16], KVLD);
                wmma::mma_sync(oacc, a1, b1, oacc);
            }
            wmma::store_matrix_sync(&Sf[hh * 4352 + mi * 16 * SLD + nj * 16],
                                    oacc, SLD, wmma::mem_row_major);
        }
        __syncthreads();

        // ---- convert O -> Oh ----
        for (int t = tid; t < 49 * 64; t += NT) {
            int r = t >> 6, cc = t & 63, hh = cc >> 5, d = cc & 31;
            Oh[r * XLD + (h0 + hh) * HDIM + d] = __float2half_rn(Sf[hh * 4352 + r * SLD + d]);
        }
        __syncthreads();
    }

    // =============== proj: out = Oh @ proj_w^T + b (hi/lo staged) ===============
    const int pm = wp & 3;          // m-tile
    const int pn0 = wp >> 2;        // first n-tile (0..3)
    const int pn1 = pn0 + 4;        // second n-tile (4..5 valid when wp<8)

    // prologue: issue p=0 chunk0 -> buf1
    {
        __half* dst = WB + WBUFH;
#pragma unroll
        for (int i = 0; i < 3; ++i)
            cpasync16(smem_u32(dst + psel[i] * PLOFF + pj[i] * WLD + pk[i]),
                      (psel[i] ? g_wpj_l : g_wpj_h) + (size_t)pj[i] * CDIM + pk[i]);
        cp_commit();
    }

    for (int p = 0; p < 4; ++p) {
        wmma::fragment<wmma::accumulator, 16, 16, 16, float> accA, accB;
        wmma::fill_fragment(accA, 0.0f);
        wmma::fill_fragment(accB, 0.0f);

        for (int c = 0; c < 6; ++c) {
            cp_wait0();
            __syncthreads();
            // issue next chunk (c+1 of this p, or chunk0 of p+1)
            if (c < 5 || p < 3) {
                int np_ = (c < 5) ? p : p + 1;
                int nc_ = (c < 5) ? c + 1 : 0;
                __half* dst = WB + (c & 1) * WBUFH;
#pragma unroll
                for (int i = 0; i < 3; ++i)
                    cpasync16(smem_u32(dst + psel[i] * PLOFF + pj[i] * WLD + pk[i]),
                              (psel[i] ? g_wpj_l : g_wpj_h)
                              + (size_t)(np_ * 96 + pj[i]) * CDIM + nc_ * 64 + pk[i]);
                cp_commit();
            }
            const __half* Wc = WB + (1 - (c & 1)) * WBUFH;
#pragma unroll
            for (int ks = 0; ks < 4; ++ks) {
                wmma::fragment<wmma::matrix_a, 16, 16, 16, __half, wmma::row_major> a1;
                wmma::load_matrix_sync(a1, &Oh[pm * 16 * XLD + c * 64 + ks * 16], XLD);
                wmma::fragment<wmma::matrix_b, 16, 16, 16, __half, wmma::col_major> bh, bl;
                wmma::load_matrix_sync(bh, &Wc[pn0 * 16 * WLD + ks * 16], WLD);
                wmma::load_matrix_sync(bl, &Wc[PLOFF + pn0 * 16 * WLD + ks * 16], WLD);
                wmma::mma_sync(accA, a1, bh, accA);
                wmma::mma_sync(accA, a1, bl, accA);
                if (wp < 8) {
                    wmma::load_matrix_sync(bh, &Wc[pn1 * 16 * WLD + ks * 16], WLD);
                    wmma::load_matrix_sync(bl, &Wc[PLOFF + pn1 * 16 * WLD + ks * 16], WLD);
                    wmma::mma_sync(accB, a1, bh, accB);
                    wmma::mma_sync(accB, a1, bl, accB);
                }
            }
        }
        wmma::store_matrix_sync(&Sf[pm * 16 * PQLD + pn0 * 16], accA, PQLD, wmma::mem_row_major);
        if (wp < 8)
            wmma::store_matrix_sync(&Sf[pm * 16 * PQLD + pn1 * 16], accB, PQLD, wmma::mem_row_major);
        __syncthreads();

        for (int t = tid; t < 49 * 96; t += NT) {
            int r = t / 96, cc = t % 96;
            out[((size_t)w * NTOK + r) * CDIM + p * 96 + cc] = Sf[r * PQLD + cc] + par[1152 + p * 96 + cc];
        }
        __syncthreads();
    }
}

// ---------------------------------------------------------------------------
extern "C" void kernel_launch(void* const* d_in, const int* in_sizes, int n_in,
                              void* d_out, int out_size)
{
    const float *x = 0, *mask = 0, *qkv_w = 0, *qkv_b = 0;
    const float *proj_w = 0, *proj_b = 0, *rpb = 0, *lamb = 0;

    for (int i = 0; i < n_in; ++i) {
        const float* p = (const float*)d_in[i];
        switch (in_sizes[i]) {
            case 77070336: x      = p; break;
            case 2458624:  mask   = p; break;
            case 442368:   qkv_w  = p; break;
            case 1152:     qkv_b  = p; break;
            case 147456:   proj_w = p; break;
            case 384:      proj_b = p; break;
            case 2028:     rpb    = p; break;
            case 12:       lamb   = p; break;
            default: break;
        }
    }
    if (!x || !mask || !qkv_w || !qkv_b || !proj_w || !proj_b || !rpb || !lamb) {
        x      = (const float*)d_in[0];
        mask   = (const float*)d_in[1];
        qkv_w  = (const float*)d_in[2];
        qkv_b  = (const float*)d_in[3];
        proj_w = (const float*)d_in[4];
        proj_b = (const float*)d_in[5];
        rpb    = (const float*)d_in[6];
        lamb   = (const float*)d_in[7];
    }

    prep_qkv_w<<<(NHEADS * 96 * CDIM + 255) / 256, 256>>>(qkv_w);
    prep_proj_w<<<(CDIM * CDIM + 255) / 256, 256>>>(proj_w);

    cudaFuncSetAttribute(winattn_kernel,
                         cudaFuncAttributeMaxDynamicSharedMemorySize, SMEM_BYTES);
    winattn_kernel<<<B_WIN, NT, SMEM_BYTES>>>(
        x, mask, qkv_b, proj_b, rpb, lamb, (float*)d_out);
}